// round 2
// baseline (speedup 1.0000x reference)
#include <cuda_runtime.h>
#include <math.h>

// Problem constants (fixed-shape problem)
#define M_TOTAL 32768      // B*S = 8*4096
#define K_DIM   512        // H
#define N_DIM   640        // G*V
#define G_NUM   2
#define V_NUM   320
#define DG      128        // D / G

// Scratch (device globals are allowed; no allocations)
__device__ float g_logits[(size_t)M_TOTAL * N_DIM];   // 80 MB
__device__ int   g_idx[M_TOTAL * G_NUM];
__device__ int   g_counts[G_NUM * V_NUM];

// ---------------------------------------------------------------------------
// Zero the histogram (graph replays require re-zeroing every launch)
// ---------------------------------------------------------------------------
__global__ void zero_counts_kernel() {
    int t = threadIdx.x;
    if (t < G_NUM * V_NUM) g_counts[t] = 0;
}

// ---------------------------------------------------------------------------
// FP32 GEMM: logits[M, N] = hs[M, K] @ W[K, N] + b[N]
// 128x128 block tile, BK=16, 256 threads, 8x8 per-thread microtile.
// ---------------------------------------------------------------------------
__global__ void gemm_kernel(const float* __restrict__ A,
                            const float* __restrict__ B,
                            const float* __restrict__ bias) {
    __shared__ float As[16][128];   // transposed A tile: As[k][m]
    __shared__ float Bs[16][128];   // Bs[k][n]

    const int bm  = blockIdx.y * 128;
    const int bn  = blockIdx.x * 128;
    const int tid = threadIdx.x;    // 0..255

    const int tm = (tid >> 4) * 8;  // 0..120
    const int tn = (tid & 15) * 8;  // 0..120

    float acc[8][8];
#pragma unroll
    for (int i = 0; i < 8; i++)
#pragma unroll
        for (int j = 0; j < 8; j++) acc[i][j] = 0.0f;

    for (int k0 = 0; k0 < K_DIM; k0 += 16) {
        // Load A tile: 128 rows x 16 cols = 512 float4 (2 per thread)
#pragma unroll
        for (int i = 0; i < 2; i++) {
            int f   = tid + i * 256;       // 0..511
            int row = f >> 2;              // 0..127
            int c4  = f & 3;               // float4 within the 16-wide row
            float4 v = *(const float4*)(A + (size_t)(bm + row) * K_DIM + k0 + c4 * 4);
            As[c4 * 4 + 0][row] = v.x;
            As[c4 * 4 + 1][row] = v.y;
            As[c4 * 4 + 2][row] = v.z;
            As[c4 * 4 + 3][row] = v.w;
        }
        // Load B tile: 16 rows x 128 cols = 512 float4 (2 per thread)
#pragma unroll
        for (int i = 0; i < 2; i++) {
            int f   = tid + i * 256;
            int row = f >> 5;              // 0..15
            int c4  = f & 31;              // 0..31
            float4 v = *(const float4*)(B + (size_t)(k0 + row) * N_DIM + bn + c4 * 4);
            *(float4*)(&Bs[row][c4 * 4]) = v;
        }
        __syncthreads();

#pragma unroll
        for (int kk = 0; kk < 16; kk++) {
            float ra[8], rb[8];
#pragma unroll
            for (int i = 0; i < 8; i++) ra[i] = As[kk][tm + i];
#pragma unroll
            for (int j = 0; j < 8; j++) rb[j] = Bs[kk][tn + j];
#pragma unroll
            for (int i = 0; i < 8; i++)
#pragma unroll
                for (int j = 0; j < 8; j++)
                    acc[i][j] = fmaf(ra[i], rb[j], acc[i][j]);
        }
        __syncthreads();
    }

    // Epilogue: add bias, store logits
#pragma unroll
    for (int i = 0; i < 8; i++) {
        float* crow = g_logits + (size_t)(bm + tm + i) * N_DIM + bn + tn;
#pragma unroll
        for (int j = 0; j < 8; j += 4) {
            float4 o;
            o.x = acc[i][j + 0] + bias[bn + tn + j + 0];
            o.y = acc[i][j + 1] + bias[bn + tn + j + 1];
            o.z = acc[i][j + 2] + bias[bn + tn + j + 2];
            o.w = acc[i][j + 3] + bias[bn + tn + j + 3];
            *(float4*)(crow + j) = o;
        }
    }
}

// ---------------------------------------------------------------------------
// Argmax over V per (token, group), one warp per (m, g).
// Tie-break: lowest index (jnp.argmax semantics).
// Also builds the histogram for the perplexity.
// ---------------------------------------------------------------------------
__global__ void argmax_kernel() {
    int warp_global = (blockIdx.x * blockDim.x + threadIdx.x) >> 5;
    int lane        = threadIdx.x & 31;
    if (warp_global >= M_TOTAL * G_NUM) return;

    int m = warp_global / G_NUM;
    int g = warp_global % G_NUM;
    const float* row = g_logits + (size_t)m * N_DIM + g * V_NUM;

    float best = -INFINITY;
    int   bi   = 0;
    for (int v = lane; v < V_NUM; v += 32) {
        float x = row[v];
        if (x > best) { best = x; bi = v; }   // strict > keeps earliest within lane
    }
#pragma unroll
    for (int off = 16; off > 0; off >>= 1) {
        float ob = __shfl_down_sync(0xffffffffu, best, off);
        int   oi = __shfl_down_sync(0xffffffffu, bi,   off);
        if (ob > best || (ob == best && oi < bi)) { best = ob; bi = oi; }
    }
    if (lane == 0) {
        g_idx[m * G_NUM + g] = bi;
        atomicAdd(&g_counts[g * V_NUM + bi], 1);
    }
}

// ---------------------------------------------------------------------------
// Gather: out[m, g*DG + d] = cb[(g*V + idx[m,g])*DG + d], vectorized float4
// ---------------------------------------------------------------------------
__global__ void gather_kernel(const float* __restrict__ cb,
                              float* __restrict__ out, int n4) {
    int e = blockIdx.x * blockDim.x + threadIdx.x;   // float4 index
    if (e >= n4) return;
    int m  = e >> 6;          // 64 float4 per output row (256 floats)
    int c4 = e & 63;
    int g  = c4 >> 5;         // 32 float4 per group chunk (128 floats)
    int d4 = c4 & 31;
    int id = g_idx[m * G_NUM + g];
    float4 v = *(const float4*)(cb + (size_t)(g * V_NUM + id) * DG + d4 * 4);
    *(float4*)(out + (size_t)e * 4) = v;
}

// ---------------------------------------------------------------------------
// Perplexity: marginal = counts / M; perp = sum_g exp(-sum_v m*log(m+1e-7))
// ---------------------------------------------------------------------------
__global__ void perp_kernel(float* __restrict__ out_p) {
    __shared__ float partial[G_NUM * V_NUM];
    int t = threadIdx.x;
    if (t < G_NUM * V_NUM) {
        float m = (float)g_counts[t] * (1.0f / (float)M_TOTAL);
        partial[t] = m * logf(m + 1e-7f);
    }
    __syncthreads();
    if (t == 0) {
        float p = 0.0f;
        for (int g = 0; g < G_NUM; g++) {
            float s = 0.0f;
            for (int v = 0; v < V_NUM; v++) s += partial[g * V_NUM + v];
            p += expf(-s);
        }
        *out_p = p;
    }
}

// ---------------------------------------------------------------------------
// Launch
// ---------------------------------------------------------------------------
extern "C" void kernel_launch(void* const* d_in, const int* in_sizes, int n_in,
                              void* d_out, int out_size) {
    const float* hs = (const float*)d_in[0];   // (B,S,H)      = 16,777,216
    const float* W  = (const float*)d_in[1];   // (H, G*V)     = 327,680
    const float* b  = (const float*)d_in[2];   // (G*V,)       = 640
    const float* cb = (const float*)d_in[3];   // (1, G*V, Dg) = 81,920
    // d_in[4] = num_groups (scalar), value fixed = 2
    float* out = (float*)d_out;

    zero_counts_kernel<<<1, G_NUM * V_NUM>>>();

    dim3 grid(N_DIM / 128, M_TOTAL / 128);   // (5, 256)
    gemm_kernel<<<grid, 256>>>(hs, W, b);

    int warps = M_TOTAL * G_NUM;             // 65536 warps
    argmax_kernel<<<(warps * 32 + 255) / 256, 256>>>();

    int n_out = M_TOTAL * G_NUM * DG;        // 8,388,608
    int n4 = n_out / 4;
    gather_kernel<<<(n4 + 255) / 256, 256>>>(cb, out, n4);

    if (out_size > n_out) {
        // perplexity appended after the flattened `out` tensor
        perp_kernel<<<1, G_NUM * V_NUM>>>(out + n_out);
    }
}

// round 4
// speedup vs baseline: 1.0710x; 1.0710x over previous
#include <cuda_runtime.h>
#include <math.h>
#include <stdint.h>

// ---------------------------------------------------------------------------
// Problem constants
// ---------------------------------------------------------------------------
#define M_TOTAL 32768      // B*S
#define K_DIM   512        // H
#define N_DIM   640        // G*V
#define G_NUM   2
#define V_NUM   320
#define DG      128

// GEMM tiling
#define BM 128
#define BN 128
#define BK 32
#define AROW 72                         // floats per A smem row (64 data + 8 pad)
#define A_SM_FLOATS (128 * AROW)        // 9216
#define B_SM_FLOATS (16 * 4 * 32 * 4)   // 8192
#define BUF_FLOATS  (A_SM_FLOATS + B_SM_FLOATS)
#define SMEM_BYTES  (2 * BUF_FLOATS * 4)   // 139264

// ---------------------------------------------------------------------------
// Device-global scratch (no allocations allowed)
// ---------------------------------------------------------------------------
__device__ float g_logits[(size_t)M_TOTAL * N_DIM];        // 80 MB
__device__ float g_asp[(size_t)M_TOTAL * K_DIM * 2];       // A split [m][k][hi,lo] 128 MB
__device__ float g_bsp[80 * 64 * 32 * 4];                  // B split, fragment-permuted
__device__ int   g_idx[M_TOTAL * G_NUM];
__device__ int   g_counts[G_NUM * V_NUM];

// ---------------------------------------------------------------------------
// Helpers
// ---------------------------------------------------------------------------
__device__ __forceinline__ float f2tf(float x) {
    uint32_t u;
    asm("cvt.rna.tf32.f32 %0, %1;" : "=r"(u) : "f"(x));
    return __uint_as_float(u);
}

__device__ __forceinline__ uint32_t smem_u32(const void* p) {
    uint32_t a;
    asm("{ .reg .u64 t; cvta.to.shared.u64 t, %1; cvt.u32.u64 %0, t; }"
        : "=r"(a) : "l"(p));
    return a;
}

__device__ __forceinline__ void cp_async16(uint32_t dst, const void* src) {
    asm volatile("cp.async.cg.shared.global [%0], [%1], 16;"
                 :: "r"(dst), "l"(src) : "memory");
}

__device__ __forceinline__ void mma8(float* c, const uint32_t* a,
                                     uint32_t b0, uint32_t b1) {
    asm volatile(
        "mma.sync.aligned.m16n8k8.row.col.f32.tf32.tf32.f32 "
        "{%0,%1,%2,%3}, {%4,%5,%6,%7}, {%8,%9}, {%0,%1,%2,%3};"
        : "+f"(c[0]), "+f"(c[1]), "+f"(c[2]), "+f"(c[3])
        : "r"(a[0]), "r"(a[1]), "r"(a[2]), "r"(a[3]), "r"(b0), "r"(b1));
}

// ---------------------------------------------------------------------------
// Pre-pass kernels
// ---------------------------------------------------------------------------
__global__ void zero_counts_kernel() {
    int t = threadIdx.x;
    if (t < G_NUM * V_NUM) g_counts[t] = 0;
}

// A fp32 -> interleaved tf32 hi/lo:  g_asp[m][k][2]
__global__ void splitA_kernel(const float* __restrict__ A) {
    size_t i = (size_t)blockIdx.x * blockDim.x + threadIdx.x;   // float4 id
    if (i >= (size_t)M_TOTAL * K_DIM / 4) return;
    float4 v = ((const float4*)A)[i];
    float h0 = f2tf(v.x), h1 = f2tf(v.y), h2 = f2tf(v.z), h3 = f2tf(v.w);
    float4 o0 = make_float4(h0, f2tf(v.x - h0), h1, f2tf(v.y - h1));
    float4 o1 = make_float4(h2, f2tf(v.z - h2), h3, f2tf(v.w - h3));
    ((float4*)g_asp)[2 * i]     = o0;
    ((float4*)g_asp)[2 * i + 1] = o1;
}

// W[k][n] fp32 -> split + permuted into per-lane mma fragment order:
//   g_bsp[ ((n>>3)*64 + (k>>3))*32 + (n&7)*4 + (k&3) ][ ((k>>2)&1)*2 + {hi,lo} ]
__global__ void splitB_kernel(const float* __restrict__ W) {
    int i = blockIdx.x * blockDim.x + threadIdx.x;   // over K*N
    if (i >= K_DIM * N_DIM) return;
    int k = i / N_DIM, n = i % N_DIM;
    float x = W[i];
    float h = f2tf(x), l = f2tf(x - h);
    int base = (((n >> 3) * 64 + (k >> 3)) * 32 + ((n & 7) * 4 + (k & 3))) * 4
             + ((k >> 2) & 1) * 2;
    g_bsp[base]     = h;
    g_bsp[base + 1] = l;
}

// ---------------------------------------------------------------------------
// 3xTF32 mma.sync GEMM: g_logits[M,N] = A @ W + bias
// grid (256, 5), 256 threads, 8 warps as 2(m) x 4(n), warp tile 64x32
// ---------------------------------------------------------------------------
__global__ __launch_bounds__(256, 1)
void gemm_tf32_kernel(const float* __restrict__ bias) {
    extern __shared__ float sm[];
    const int tid  = threadIdx.x;
    const int wid  = tid >> 5;
    const int lane = tid & 31;
    const int g    = lane >> 2;       // groupID
    const int t    = lane & 3;        // threadID_in_group
    const int wm   = (wid & 1) * 64;
    const int wn   = (wid >> 1) * 32;
    const int bm   = blockIdx.x * BM;
    const int by   = blockIdx.y;
    const int bn   = by * BN;

    const uint32_t sb = smem_u32(sm);

    float acc[4][4][4];
#pragma unroll
    for (int a = 0; a < 4; a++)
#pragma unroll
        for (int b = 0; b < 4; b++)
#pragma unroll
            for (int c = 0; c < 4; c++) acc[a][b][c] = 0.0f;

    // ---- async tile loader ----
    auto load_stage = [&](int s, int buf) {
        uint32_t Asm = sb + buf * (BUF_FLOATS * 4);
        uint32_t Bsm = Asm + A_SM_FLOATS * 4;
        // A: 2048 chunks of 16B
#pragma unroll
        for (int i = 0; i < 8; i++) {
            int c   = tid + i * 256;
            int row = c >> 4;
            int cib = c & 15;
            const float* src = g_asp + (size_t)(bm + row) * (K_DIM * 2) + s * (BK * 2) + cib * 4;
            cp_async16(Asm + (row * AROW + cib * 4) * 4, src);
        }
        // B: 2048 chunks of 16B (already in destination order)
#pragma unroll
        for (int i = 0; i < 8; i++) {
            int c  = tid + i * 256;
            int nt = c >> 7;
            int kt = (c >> 5) & 3;
            int ln = c & 31;
            const float* src = g_bsp + ((((by * 16 + nt) * 64) + s * 4 + kt) * 32 + ln) * 4;
            cp_async16(Bsm + c * 16, src);
        }
        asm volatile("cp.async.commit_group;" ::: "memory");
    };

    // ---- compute one k-stage from smem ----
    auto compute = [&](int buf) {
        const float* As = sm + buf * BUF_FLOATS;
        const float* Bs = As + A_SM_FLOATS;
#pragma unroll
        for (int kt = 0; kt < 4; kt++) {
            uint32_t ahi[4][4], alo[4][4];
#pragma unroll
            for (int mt = 0; mt < 4; mt++) {
                int r0 = wm + mt * 16 + g;
                int c0 = kt * 8 + t;
                float2 v0 = *(const float2*)(As + r0 * AROW + c0 * 2);
                float2 v1 = *(const float2*)(As + (r0 + 8) * AROW + c0 * 2);
                float2 v2 = *(const float2*)(As + r0 * AROW + (c0 + 4) * 2);
                float2 v3 = *(const float2*)(As + (r0 + 8) * AROW + (c0 + 4) * 2);
                ahi[mt][0] = __float_as_uint(v0.x); alo[mt][0] = __float_as_uint(v0.y);
                ahi[mt][1] = __float_as_uint(v1.x); alo[mt][1] = __float_as_uint(v1.y);
                ahi[mt][2] = __float_as_uint(v2.x); alo[mt][2] = __float_as_uint(v2.y);
                ahi[mt][3] = __float_as_uint(v3.x); alo[mt][3] = __float_as_uint(v3.y);
            }
            uint32_t bf[4][4];
#pragma unroll
            for (int nt = 0; nt < 4; nt++) {
                // global n8-tile index within CTA = wn/8 + nt
                float4 bv = *(const float4*)(Bs + (((wn >> 3) + nt) * 4 + kt) * 128 + lane * 4);
                bf[nt][0] = __float_as_uint(bv.x);   // b0 hi
                bf[nt][1] = __float_as_uint(bv.y);   // b0 lo
                bf[nt][2] = __float_as_uint(bv.z);   // b1 hi
                bf[nt][3] = __float_as_uint(bv.w);   // b1 lo
            }
#pragma unroll
            for (int mt = 0; mt < 4; mt++)
#pragma unroll
                for (int nt = 0; nt < 4; nt++) {
                    mma8(acc[mt][nt], ahi[mt], bf[nt][0], bf[nt][2]);  // hh
                    mma8(acc[mt][nt], ahi[mt], bf[nt][1], bf[nt][3]);  // h*lo
                    mma8(acc[mt][nt], alo[mt], bf[nt][0], bf[nt][2]);  // lo*h
                }
        }
    };

    // ---- 2-stage pipeline over 16 k-stages ----
    load_stage(0, 0);
    load_stage(1, 1);
    for (int s = 0; s < 16; s++) {
        if (s == 15) asm volatile("cp.async.wait_group 0;" ::: "memory");
        else         asm volatile("cp.async.wait_group 1;" ::: "memory");
        __syncthreads();
        compute(s & 1);
        __syncthreads();
        if (s + 2 < 16) load_stage(s + 2, s & 1);
    }

    // ---- epilogue: bias + store logits ----
#pragma unroll
    for (int nt = 0; nt < 4; nt++) {
        int col = bn + wn + nt * 8 + 2 * t;
        float b0 = bias[col], b1 = bias[col + 1];
#pragma unroll
        for (int mt = 0; mt < 4; mt++) {
            int row = bm + wm + mt * 16 + g;
            float2 lo2 = make_float2(acc[mt][nt][0] + b0, acc[mt][nt][1] + b1);
            float2 hi2 = make_float2(acc[mt][nt][2] + b0, acc[mt][nt][3] + b1);
            *(float2*)(g_logits + (size_t)row * N_DIM + col)       = lo2;
            *(float2*)(g_logits + (size_t)(row + 8) * N_DIM + col) = hi2;
        }
    }
}

// ---------------------------------------------------------------------------
// Argmax per (token, group): one warp per (m, g); earliest index on ties.
// ---------------------------------------------------------------------------
__global__ void argmax_kernel() {
    int warp_global = (blockIdx.x * blockDim.x + threadIdx.x) >> 5;
    int lane        = threadIdx.x & 31;
    if (warp_global >= M_TOTAL * G_NUM) return;

    int m = warp_global / G_NUM;
    int g = warp_global % G_NUM;
    const float* row = g_logits + (size_t)m * N_DIM + g * V_NUM;

    float best = -INFINITY;
    int   bi   = 0;
    for (int v = lane; v < V_NUM; v += 32) {
        float x = row[v];
        if (x > best) { best = x; bi = v; }
    }
#pragma unroll
    for (int off = 16; off > 0; off >>= 1) {
        float ob = __shfl_down_sync(0xffffffffu, best, off);
        int   oi = __shfl_down_sync(0xffffffffu, bi,   off);
        if (ob > best || (ob == best && oi < bi)) { best = ob; bi = oi; }
    }
    if (lane == 0) {
        g_idx[m * G_NUM + g] = bi;
        atomicAdd(&g_counts[g * V_NUM + bi], 1);
    }
}

// ---------------------------------------------------------------------------
// Gather codevectors
// ---------------------------------------------------------------------------
__global__ void gather_kernel(const float* __restrict__ cb,
                              float* __restrict__ out, int n4) {
    int e = blockIdx.x * blockDim.x + threadIdx.x;
    if (e >= n4) return;
    int m  = e >> 6;
    int c4 = e & 63;
    int g  = c4 >> 5;
    int d4 = c4 & 31;
    int id = g_idx[m * G_NUM + g];
    float4 v = *(const float4*)(cb + (size_t)(g * V_NUM + id) * DG + d4 * 4);
    *(float4*)(out + (size_t)e * 4) = v;
}

// ---------------------------------------------------------------------------
// Perplexity
// ---------------------------------------------------------------------------
__global__ void perp_kernel(float* __restrict__ out_p) {
    __shared__ float partial[G_NUM * V_NUM];
    int t = threadIdx.x;
    if (t < G_NUM * V_NUM) {
        float m = (float)g_counts[t] * (1.0f / (float)M_TOTAL);
        partial[t] = m * logf(m + 1e-7f);
    }
    __syncthreads();
    if (t == 0) {
        float p = 0.0f;
        for (int g = 0; g < G_NUM; g++) {
            float s = 0.0f;
            for (int v = 0; v < V_NUM; v++) s += partial[g * V_NUM + v];
            p += expf(-s);
        }
        *out_p = p;
    }
}

// ---------------------------------------------------------------------------
// Launch
// ---------------------------------------------------------------------------
extern "C" void kernel_launch(void* const* d_in, const int* in_sizes, int n_in,
                              void* d_out, int out_size) {
    const float* hs = (const float*)d_in[0];   // (B,S,H)
    const float* W  = (const float*)d_in[1];   // (H, G*V)
    const float* b  = (const float*)d_in[2];   // (G*V,)
    const float* cb = (const float*)d_in[3];   // (1, G*V, Dg)
    float* out = (float*)d_out;

    cudaFuncSetAttribute(gemm_tf32_kernel,
                         cudaFuncAttributeMaxDynamicSharedMemorySize, SMEM_BYTES);

    zero_counts_kernel<<<1, G_NUM * V_NUM>>>();
    splitA_kernel<<<(M_TOTAL * K_DIM / 4 + 255) / 256, 256>>>(hs);
    splitB_kernel<<<(K_DIM * N_DIM + 255) / 256, 256>>>(W);

    dim3 grid(M_TOTAL / BM, N_DIM / BN);   // (256, 5)
    gemm_tf32_kernel<<<grid, 256, SMEM_BYTES>>>(b);

    int warps = M_TOTAL * G_NUM;
    argmax_kernel<<<(warps * 32 + 255) / 256, 256>>>();

    int n_out = M_TOTAL * G_NUM * DG;
    int n4 = n_out / 4;
    gather_kernel<<<(n4 + 255) / 256, 256>>>(cb, out, n4);

    if (out_size > n_out) {
        perp_kernel<<<1, G_NUM * V_NUM>>>(out + n_out);
    }
}

// round 5
// speedup vs baseline: 1.1944x; 1.1153x over previous
#include <cuda_runtime.h>
#include <math.h>
#include <stdint.h>

// ---------------------------------------------------------------------------
// Problem constants
// ---------------------------------------------------------------------------
#define M_TOTAL 32768      // B*S
#define K_DIM   512        // H
#define N_DIM   640        // G*V
#define G_NUM   2
#define V_NUM   320
#define DG      128

// GEMM tiling
#define BM 128
#define BN 128
#define BK 16
#define NKSTAGES (K_DIM / BK)          // 32
#define AROW 36                         // floats per A smem row (32 data + 4 pad)
#define A_SM_BYTES (128 * AROW * 4)     // 18432
#define B_SM_BYTES (16 * 2 * 32 * 16)   // 16384
#define STAGE_BYTES (A_SM_BYTES + B_SM_BYTES)   // 34816
#define NSTAGES 3
#define SMEM_BYTES (NSTAGES * STAGE_BYTES)      // 104448

// ---------------------------------------------------------------------------
// Device-global scratch (no allocations allowed)
// ---------------------------------------------------------------------------
__device__ float g_asp[(size_t)M_TOTAL * K_DIM * 2];       // A split [m][k][hi,lo]
__device__ float g_bsp[80 * 64 * 32 * 4];                  // B split, frag-permuted
__device__ unsigned long long g_best[M_TOTAL * G_NUM];     // packed (val, ~col)
__device__ int g_idx[M_TOTAL * G_NUM];
__device__ int g_counts[G_NUM * V_NUM];

// ---------------------------------------------------------------------------
// Helpers
// ---------------------------------------------------------------------------
__device__ __forceinline__ float f2tf(float x) {
    uint32_t u;
    asm("cvt.rna.tf32.f32 %0, %1;" : "=r"(u) : "f"(x));
    return __uint_as_float(u);
}

__device__ __forceinline__ uint32_t smem_u32(const void* p) {
    uint32_t a;
    asm("{ .reg .u64 t; cvta.to.shared.u64 t, %1; cvt.u32.u64 %0, t; }"
        : "=r"(a) : "l"(p));
    return a;
}

__device__ __forceinline__ void cp_async16(uint32_t dst, const void* src) {
    asm volatile("cp.async.cg.shared.global [%0], [%1], 16;"
                 :: "r"(dst), "l"(src) : "memory");
}

__device__ __forceinline__ void mma8(float* c, const uint32_t* a,
                                     uint32_t b0, uint32_t b1) {
    asm volatile(
        "mma.sync.aligned.m16n8k8.row.col.f32.tf32.tf32.f32 "
        "{%0,%1,%2,%3}, {%4,%5,%6,%7}, {%8,%9}, {%0,%1,%2,%3};"
        : "+f"(c[0]), "+f"(c[1]), "+f"(c[2]), "+f"(c[3])
        : "r"(a[0]), "r"(a[1]), "r"(a[2]), "r"(a[3]), "r"(b0), "r"(b1));
}

__device__ __forceinline__ uint32_t ordf(float v) {
    uint32_t u = __float_as_uint(v);
    return (u & 0x80000000u) ? ~u : (u | 0x80000000u);
}

// ---------------------------------------------------------------------------
// Init + pre-pass kernels
// ---------------------------------------------------------------------------
__global__ void init_kernel() {
    int i = blockIdx.x * blockDim.x + threadIdx.x;
    if (i < M_TOTAL * G_NUM) g_best[i] = 0ull;
    if (i < G_NUM * V_NUM) g_counts[i] = 0;
}

// A fp32 -> interleaved tf32 hi/lo:  g_asp[m][k][2]
__global__ void splitA_kernel(const float* __restrict__ A) {
    size_t i = (size_t)blockIdx.x * blockDim.x + threadIdx.x;   // float4 id
    if (i >= (size_t)M_TOTAL * K_DIM / 4) return;
    float4 v = ((const float4*)A)[i];
    float h0 = f2tf(v.x), h1 = f2tf(v.y), h2 = f2tf(v.z), h3 = f2tf(v.w);
    float4 o0 = make_float4(h0, f2tf(v.x - h0), h1, f2tf(v.y - h1));
    float4 o1 = make_float4(h2, f2tf(v.z - h2), h3, f2tf(v.w - h3));
    ((float4*)g_asp)[2 * i]     = o0;
    ((float4*)g_asp)[2 * i + 1] = o1;
}

// W[k][n] fp32 -> split + permuted into per-lane mma fragment order
__global__ void splitB_kernel(const float* __restrict__ W) {
    int i = blockIdx.x * blockDim.x + threadIdx.x;   // over K*N
    if (i >= K_DIM * N_DIM) return;
    int k = i / N_DIM, n = i % N_DIM;
    float x = W[i];
    float h = f2tf(x), l = f2tf(x - h);
    int base = (((n >> 3) * 64 + (k >> 3)) * 32 + ((n & 7) * 4 + (k & 3))) * 4
             + ((k >> 2) & 1) * 2;
    g_bsp[base]     = h;
    g_bsp[base + 1] = l;
}

// ---------------------------------------------------------------------------
// 3xTF32 mma.sync GEMM with fused bias + argmax (packed atomicMax)
// grid (256, 5), 256 threads, 8 warps as 2(m) x 4(n), warp tile 64x32
// ---------------------------------------------------------------------------
__global__ __launch_bounds__(256, 2)
void gemm_tf32_kernel(const float* __restrict__ bias) {
    extern __shared__ float sm[];
    const int tid  = threadIdx.x;
    const int wid  = tid >> 5;
    const int lane = tid & 31;
    const int g    = lane >> 2;       // groupID (row within 8)
    const int t    = lane & 3;        // threadID_in_group (col pair / k)
    const int wm   = (wid & 1) * 64;
    const int wn   = (wid >> 1) * 32;
    const int bm   = blockIdx.x * BM;
    const int by   = blockIdx.y;
    const int bn   = by * BN;

    const uint32_t sb = smem_u32(sm);

    float acc[4][4][4];
#pragma unroll
    for (int a = 0; a < 4; a++)
#pragma unroll
        for (int b = 0; b < 4; b++)
#pragma unroll
            for (int c = 0; c < 4; c++) acc[a][b][c] = 0.0f;

    // ---- async stage loader (one commit group per stage) ----
    auto load_stage = [&](int s) {
        int buf = s % NSTAGES;
        uint32_t Asm = sb + buf * STAGE_BYTES;
        uint32_t Bsm = Asm + A_SM_BYTES;
        // A: 1024 chunks of 16B (128 rows x 8 chunks)
#pragma unroll
        for (int i = 0; i < 4; i++) {
            int c   = tid + i * 256;
            int row = c >> 3;
            int q   = c & 7;
            const float* src = g_asp + (size_t)(bm + row) * (K_DIM * 2)
                             + s * (BK * 2) + q * 4;
            cp_async16(Asm + row * (AROW * 4) + q * 16, src);
        }
        // B: 1024 chunks of 16B ([nt 16][k8 2][lane 32])
#pragma unroll
        for (int i = 0; i < 4; i++) {
            int c  = tid + i * 256;
            int nt = c >> 6;
            int k8 = (c >> 5) & 1;
            int ln = c & 31;
            const float* src = g_bsp + ((((by * 16 + nt) * 64) + s * 2 + k8) * 32 + ln) * 4;
            cp_async16(Bsm + c * 16, src);
        }
        asm volatile("cp.async.commit_group;" ::: "memory");
    };

    // ---- compute one BK=16 stage from smem ----
    auto compute = [&](int buf) {
        const float* As = sm + buf * (STAGE_BYTES / 4);
        const float* Bs = As + (A_SM_BYTES / 4);
#pragma unroll
        for (int kt = 0; kt < 2; kt++) {
            uint32_t ahi[4][4], alo[4][4];
#pragma unroll
            for (int mt = 0; mt < 4; mt++) {
                int r0 = wm + mt * 16 + g;
                int c0 = kt * 8 + t;
                float2 v0 = *(const float2*)(As + r0 * AROW + c0 * 2);
                float2 v1 = *(const float2*)(As + (r0 + 8) * AROW + c0 * 2);
                float2 v2 = *(const float2*)(As + r0 * AROW + (c0 + 4) * 2);
                float2 v3 = *(const float2*)(As + (r0 + 8) * AROW + (c0 + 4) * 2);
                ahi[mt][0] = __float_as_uint(v0.x); alo[mt][0] = __float_as_uint(v0.y);
                ahi[mt][1] = __float_as_uint(v1.x); alo[mt][1] = __float_as_uint(v1.y);
                ahi[mt][2] = __float_as_uint(v2.x); alo[mt][2] = __float_as_uint(v2.y);
                ahi[mt][3] = __float_as_uint(v3.x); alo[mt][3] = __float_as_uint(v3.y);
            }
            uint32_t bf[4][4];
#pragma unroll
            for (int nt = 0; nt < 4; nt++) {
                float4 bv = *(const float4*)(Bs + ((((wn >> 3) + nt) * 2 + kt) * 32 + lane) * 4);
                bf[nt][0] = __float_as_uint(bv.x);
                bf[nt][1] = __float_as_uint(bv.y);
                bf[nt][2] = __float_as_uint(bv.z);
                bf[nt][3] = __float_as_uint(bv.w);
            }
#pragma unroll
            for (int mt = 0; mt < 4; mt++)
#pragma unroll
                for (int nt = 0; nt < 4; nt++) {
                    mma8(acc[mt][nt], ahi[mt], bf[nt][0], bf[nt][2]);  // hh
                    mma8(acc[mt][nt], ahi[mt], bf[nt][1], bf[nt][3]);  // h*lo
                    mma8(acc[mt][nt], alo[mt], bf[nt][0], bf[nt][2]);  // lo*h
                }
        }
    };

    // ---- 3-stage pipeline over 32 k-stages, one barrier per stage ----
    load_stage(0);
    load_stage(1);
    for (int s = 0; s < NKSTAGES; s++) {
        if (s < NKSTAGES - 2)
            asm volatile("cp.async.wait_group 1;" ::: "memory");
        else
            asm volatile("cp.async.wait_group 0;" ::: "memory");
        __syncthreads();
        if (s + 2 < NKSTAGES) load_stage(s + 2);
        compute(s % NSTAGES);
    }

    // ---- fused epilogue: bias + packed argmax + atomicMax ----
    // Warp's 32-col slice never crosses the 320-col group boundary (32 | 320).
    const int gcol    = ((bn + wn) >= V_NUM) ? 1 : 0;
    const int colbase = bn + wn - gcol * V_NUM;

    unsigned long long best[8];   // [mt][half]
#pragma unroll
    for (int i = 0; i < 8; i++) best[i] = 0ull;

#pragma unroll
    for (int nt = 0; nt < 4; nt++) {
        int colg = colbase + nt * 8 + 2 * t;          // col within group
        float b0 = bias[bn + wn + nt * 8 + 2 * t];
        float b1 = bias[bn + wn + nt * 8 + 2 * t + 1];
#pragma unroll
        for (int mt = 0; mt < 4; mt++) {
            float v0 = acc[mt][nt][0] + b0;
            float v1 = acc[mt][nt][1] + b1;
            float v2 = acc[mt][nt][2] + b0;
            float v3 = acc[mt][nt][3] + b1;
            unsigned long long c0 = ((unsigned long long)ordf(v0) << 32) | (uint32_t)(~colg);
            unsigned long long c1 = ((unsigned long long)ordf(v1) << 32) | (uint32_t)(~(colg + 1));
            unsigned long long c2 = ((unsigned long long)ordf(v2) << 32) | (uint32_t)(~colg);
            unsigned long long c3 = ((unsigned long long)ordf(v3) << 32) | (uint32_t)(~(colg + 1));
            if (c0 > best[mt * 2])     best[mt * 2]     = c0;
            if (c1 > best[mt * 2])     best[mt * 2]     = c1;
            if (c2 > best[mt * 2 + 1]) best[mt * 2 + 1] = c2;
            if (c3 > best[mt * 2 + 1]) best[mt * 2 + 1] = c3;
        }
    }
    // reduce across the 4 t-lanes (same rows)
#pragma unroll
    for (int i = 0; i < 8; i++) {
        unsigned long long o1 = __shfl_xor_sync(0xffffffffu, best[i], 1);
        if (o1 > best[i]) best[i] = o1;
        unsigned long long o2 = __shfl_xor_sync(0xffffffffu, best[i], 2);
        if (o2 > best[i]) best[i] = o2;
    }
    if (t == 0) {
#pragma unroll
        for (int mt = 0; mt < 4; mt++) {
#pragma unroll
            for (int half = 0; half < 2; half++) {
                int row = bm + wm + mt * 16 + g + half * 8;
                atomicMax(&g_best[row * G_NUM + gcol], best[mt * 2 + half]);
            }
        }
    }
}

// ---------------------------------------------------------------------------
// Extract argmax indices + histogram from packed bests
// ---------------------------------------------------------------------------
__global__ void extract_kernel() {
    int i = blockIdx.x * blockDim.x + threadIdx.x;
    if (i >= M_TOTAL * G_NUM) return;
    unsigned long long b = g_best[i];
    int col = (int)(~(uint32_t)b);
    g_idx[i] = col;
    atomicAdd(&g_counts[(i & 1) * V_NUM + col], 1);
}

// ---------------------------------------------------------------------------
// Gather codevectors
// ---------------------------------------------------------------------------
__global__ void gather_kernel(const float* __restrict__ cb,
                              float* __restrict__ out, int n4) {
    int e = blockIdx.x * blockDim.x + threadIdx.x;
    if (e >= n4) return;
    int m  = e >> 6;
    int c4 = e & 63;
    int g  = c4 >> 5;
    int d4 = c4 & 31;
    int id = g_idx[m * G_NUM + g];
    float4 v = *(const float4*)(cb + (size_t)(g * V_NUM + id) * DG + d4 * 4);
    *(float4*)(out + (size_t)e * 4) = v;
}

// ---------------------------------------------------------------------------
// Perplexity
// ---------------------------------------------------------------------------
__global__ void perp_kernel(float* __restrict__ out_p) {
    __shared__ float partial[G_NUM * V_NUM];
    int t = threadIdx.x;
    if (t < G_NUM * V_NUM) {
        float m = (float)g_counts[t] * (1.0f / (float)M_TOTAL);
        partial[t] = m * logf(m + 1e-7f);
    }
    __syncthreads();
    if (t == 0) {
        float p = 0.0f;
        for (int g = 0; g < G_NUM; g++) {
            float s = 0.0f;
            for (int v = 0; v < V_NUM; v++) s += partial[g * V_NUM + v];
            p += expf(-s);
        }
        *out_p = p;
    }
}

// ---------------------------------------------------------------------------
// Launch
// ---------------------------------------------------------------------------
extern "C" void kernel_launch(void* const* d_in, const int* in_sizes, int n_in,
                              void* d_out, int out_size) {
    const float* hs = (const float*)d_in[0];   // (B,S,H)
    const float* W  = (const float*)d_in[1];   // (H, G*V)
    const float* b  = (const float*)d_in[2];   // (G*V,)
    const float* cb = (const float*)d_in[3];   // (1, G*V, Dg)
    float* out = (float*)d_out;

    cudaFuncSetAttribute(gemm_tf32_kernel,
                         cudaFuncAttributeMaxDynamicSharedMemorySize, SMEM_BYTES);

    init_kernel<<<(M_TOTAL * G_NUM + 255) / 256, 256>>>();
    splitA_kernel<<<(M_TOTAL * K_DIM / 4 + 255) / 256, 256>>>(hs);
    splitB_kernel<<<(K_DIM * N_DIM + 255) / 256, 256>>>(W);

    dim3 grid(M_TOTAL / BM, N_DIM / BN);   // (256, 5)
    gemm_tf32_kernel<<<grid, 256, SMEM_BYTES>>>(b);

    extract_kernel<<<(M_TOTAL * G_NUM + 255) / 256, 256>>>();

    int n_out = M_TOTAL * G_NUM * DG;
    int n4 = n_out / 4;
    gather_kernel<<<(n4 + 255) / 256, 256>>>(cb, out, n4);

    if (out_size > n_out) {
        perp_kernel<<<1, G_NUM * V_NUM>>>(out + n_out);
    }
}

// round 6
// speedup vs baseline: 2.1615x; 1.8097x over previous
#include <cuda_runtime.h>
#include <cuda_fp16.h>
#include <math.h>
#include <stdint.h>

// ---------------------------------------------------------------------------
// Problem constants
// ---------------------------------------------------------------------------
#define M_TOTAL 32768      // B*S
#define K_DIM   512        // H
#define N_DIM   640        // G*V
#define G_NUM   2
#define V_NUM   320
#define DG      128
#define WSCALE  64.0f      // pre-scale on W and bias (argmax-invariant)

// GEMM tiling
#define BM 128
#define BN 128
#define BK 32
#define NKS (K_DIM / BK)        // 16 k-stages
#define A_ST 16384              // A stage bytes: 128 rows x 128B
#define B_ST 16384              // B stage bytes: 16 nt x 2 kb x 32 lanes x 16B
#define STAGE (A_ST + B_ST)     // 32768
#define NSTG 3
#define SMEM_BYTES (NSTG * STAGE)   // 98304

// ---------------------------------------------------------------------------
// Device-global scratch
// ---------------------------------------------------------------------------
__device__ uint4 g_asp[(size_t)M_TOTAL * 32 * 4];   // A split: per (m,kb16): h[16],m[16] = 64B
__device__ uint4 g_bsp[80 * 32 * 32];               // B split, frag-permuted: [nt][kb][lane]
__device__ unsigned long long g_best[M_TOTAL * G_NUM];
__device__ int g_idx[M_TOTAL * G_NUM];
__device__ int g_counts[G_NUM * V_NUM];

// ---------------------------------------------------------------------------
// Helpers
// ---------------------------------------------------------------------------
__device__ __forceinline__ uint32_t smem_u32(const void* p) {
    uint32_t a;
    asm("{ .reg .u64 t; cvta.to.shared.u64 t, %1; cvt.u32.u64 %0, t; }"
        : "=r"(a) : "l"(p));
    return a;
}

__device__ __forceinline__ void cp_async16(uint32_t dst, const void* src) {
    asm volatile("cp.async.cg.shared.global [%0], [%1], 16;"
                 :: "r"(dst), "l"(src) : "memory");
}

__device__ __forceinline__ void ldm_x4(uint32_t* r, uint32_t addr) {
    asm volatile("ldmatrix.sync.aligned.m8n8.x4.shared.b16 {%0,%1,%2,%3}, [%4];"
                 : "=r"(r[0]), "=r"(r[1]), "=r"(r[2]), "=r"(r[3]) : "r"(addr));
}

__device__ __forceinline__ void mma16(float* c, const uint32_t* a,
                                      uint32_t b0, uint32_t b1) {
    asm volatile(
        "mma.sync.aligned.m16n8k16.row.col.f32.f16.f16.f32 "
        "{%0,%1,%2,%3},{%4,%5,%6,%7},{%8,%9},{%0,%1,%2,%3};"
        : "+f"(c[0]), "+f"(c[1]), "+f"(c[2]), "+f"(c[3])
        : "r"(a[0]), "r"(a[1]), "r"(a[2]), "r"(a[3]), "r"(b0), "r"(b1));
}

__device__ __forceinline__ uint32_t packh2(__half a, __half b) {
    __half2 t = __halves2half2(a, b);
    return *reinterpret_cast<uint32_t*>(&t);
}

__device__ __forceinline__ uint32_t ordf(float v) {
    uint32_t u = __float_as_uint(v);
    return (u & 0x80000000u) ? ~u : (u | 0x80000000u);
}

// ---------------------------------------------------------------------------
// Init + pre-pass kernels
// ---------------------------------------------------------------------------
__global__ void init_kernel() {
    int i = blockIdx.x * blockDim.x + threadIdx.x;
    if (i < M_TOTAL * G_NUM) g_best[i] = 0ull;
    if (i < G_NUM * V_NUM) g_counts[i] = 0;
}

// A fp32 -> fp16 (h, m) per 16-k block: layout per (m, kb): [h 32B][m 32B]
__global__ void splitA_kernel(const float* __restrict__ A) {
    int id = blockIdx.x * blockDim.x + threadIdx.x;   // m*32 + kb
    if (id >= M_TOTAL * 32) return;
    const float* src = A + (size_t)id * 16;
    uint32_t hp[8], mp[8];
#pragma unroll
    for (int e = 0; e < 8; e++) {
        float x0 = src[2 * e], x1 = src[2 * e + 1];
        __half h0 = __float2half_rn(x0);
        __half h1 = __float2half_rn(x1);
        __half m0 = __float2half_rn(x0 - __half2float(h0));
        __half m1 = __float2half_rn(x1 - __half2float(h1));
        hp[e] = packh2(h0, h1);
        mp[e] = packh2(m0, m1);
    }
    uint4* dst = g_asp + (size_t)id * 4;
    dst[0] = make_uint4(hp[0], hp[1], hp[2], hp[3]);
    dst[1] = make_uint4(hp[4], hp[5], hp[6], hp[7]);
    dst[2] = make_uint4(mp[0], mp[1], mp[2], mp[3]);
    dst[3] = make_uint4(mp[4], mp[5], mp[6], mp[7]);
}

// W[k][n]*64 -> fp16 (h, m) b-fragments in exact per-lane mma order
__global__ void splitB_kernel(const float* __restrict__ W) {
    int id = blockIdx.x * blockDim.x + threadIdx.x;
    if (id >= 80 * 32 * 32) return;
    int l   = id & 31;
    int kb  = (id >> 5) & 31;
    int ntg = id >> 10;
    int k0  = kb * 16 + (l & 3) * 2;
    int n   = ntg * 8 + (l >> 2);

    float w0 = W[(size_t)(k0)     * N_DIM + n] * WSCALE;
    float w1 = W[(size_t)(k0 + 1) * N_DIM + n] * WSCALE;
    float w8 = W[(size_t)(k0 + 8) * N_DIM + n] * WSCALE;
    float w9 = W[(size_t)(k0 + 9) * N_DIM + n] * WSCALE;

    __half h0 = __float2half_rn(w0), h1 = __float2half_rn(w1);
    __half h8 = __float2half_rn(w8), h9 = __float2half_rn(w9);
    __half m0 = __float2half_rn(w0 - __half2float(h0));
    __half m1 = __float2half_rn(w1 - __half2float(h1));
    __half m8 = __float2half_rn(w8 - __half2float(h8));
    __half m9 = __float2half_rn(w9 - __half2float(h9));

    g_bsp[id] = make_uint4(packh2(h0, h1), packh2(h8, h9),
                           packh2(m0, m1), packh2(m8, m9));
}

// ---------------------------------------------------------------------------
// fp16x2-split 4-term GEMM with fused bias + argmax
// grid (256, 5), 256 threads, 8 warps 2(m) x 4(n), warp tile 64x32
// ---------------------------------------------------------------------------
__global__ __launch_bounds__(256, 2)
void gemm_fp16_kernel(const float* __restrict__ bias) {
    extern __shared__ char smem[];
    const uint32_t sb = smem_u32(smem);
    const int tid  = threadIdx.x;
    const int wid  = tid >> 5;
    const int lane = tid & 31;
    const int g    = lane >> 2;       // C row within 8
    const int t    = lane & 3;        // C col pair
    const int wm   = (wid & 1) * 64;
    const int wn   = (wid >> 1) * 32;
    const int bm   = blockIdx.x * BM;
    const int by   = blockIdx.y;
    const int bn   = by * BN;

    // ldmatrix row/chunk assignment for this lane
    const int lrow_off = ((lane >> 3) & 1) * 8 + (lane & 7);
    const int lkh      = lane >> 4;   // 0..1 : which 16B chunk of the k16

    float acc[4][4][4];
#pragma unroll
    for (int a = 0; a < 4; a++)
#pragma unroll
        for (int b = 0; b < 4; b++)
#pragma unroll
            for (int c = 0; c < 4; c++) acc[a][b][c] = 0.0f;

    auto load_stage = [&](int s) {
        int buf = s % NSTG;
        uint32_t Asm = sb + buf * STAGE;
        uint32_t Bsm = Asm + A_ST;
        // A: 1024 x 16B, SW128 XOR swizzle
#pragma unroll
        for (int i = 0; i < 4; i++) {
            int c   = tid + i * 256;
            int row = c >> 3;
            int q   = c & 7;
            const char* src = (const char*)g_asp + (size_t)(bm + row) * 2048
                            + s * 128 + q * 16;
            cp_async16(Asm + row * 128 + ((q ^ (row & 7)) * 16), src);
        }
        // B: 1024 x 16B, already fragment-ordered
#pragma unroll
        for (int i = 0; i < 4; i++) {
            int c  = tid + i * 256;
            int nt = c >> 6;
            int j  = (c >> 5) & 1;
            int ln = c & 31;
            const char* src = (const char*)g_bsp +
                ((size_t)((by * 16 + nt) * 32 + s * 2 + j) * 32 + ln) * 16;
            cp_async16(Bsm + c * 16, src);
        }
        asm volatile("cp.async.commit_group;" ::: "memory");
    };

    auto compute = [&](int buf) {
        uint32_t Asm = sb + buf * STAGE;
        const uint4* Bp = (const uint4*)(smem + buf * STAGE + A_ST);
#pragma unroll
        for (int j = 0; j < 2; j++) {
            uint32_t ah[4][4], am[4][4];
#pragma unroll
            for (int mt = 0; mt < 4; mt++) {
                int row = wm + mt * 16 + lrow_off;
                uint32_t base = Asm + row * 128;
                uint32_t ch = ((j << 2) + lkh)     ^ (row & 7);
                uint32_t cm = ((j << 2) + 2 + lkh) ^ (row & 7);
                ldm_x4(ah[mt], base + ch * 16);
                ldm_x4(am[mt], base + cm * 16);
            }
            uint4 bv[4];
#pragma unroll
            for (int nt = 0; nt < 4; nt++)
                bv[nt] = Bp[(((wn >> 3) + nt) * 2 + j) * 32 + lane];
#pragma unroll
            for (int mt = 0; mt < 4; mt++)
#pragma unroll
                for (int nt = 0; nt < 4; nt++) {
                    mma16(acc[mt][nt], ah[mt], bv[nt].x, bv[nt].y);  // hh
                    mma16(acc[mt][nt], ah[mt], bv[nt].z, bv[nt].w);  // hm
                    mma16(acc[mt][nt], am[mt], bv[nt].x, bv[nt].y);  // mh
                    mma16(acc[mt][nt], am[mt], bv[nt].z, bv[nt].w);  // mm
                }
        }
    };

    load_stage(0);
    load_stage(1);
    for (int s = 0; s < NKS; s++) {
        if (s < NKS - 2)
            asm volatile("cp.async.wait_group 1;" ::: "memory");
        else
            asm volatile("cp.async.wait_group 0;" ::: "memory");
        __syncthreads();
        if (s + 2 < NKS) load_stage(s + 2);
        compute(s % NSTG);
    }

    // ---- fused epilogue: scaled bias + packed argmax + atomicMax ----
    const int gcol    = ((bn + wn) >= V_NUM) ? 1 : 0;
    const int colbase = bn + wn - gcol * V_NUM;

    unsigned long long best[8];
#pragma unroll
    for (int i = 0; i < 8; i++) best[i] = 0ull;

#pragma unroll
    for (int nt = 0; nt < 4; nt++) {
        int colg = colbase + nt * 8 + 2 * t;
        float b0 = bias[bn + wn + nt * 8 + 2 * t]     * WSCALE;
        float b1 = bias[bn + wn + nt * 8 + 2 * t + 1] * WSCALE;
#pragma unroll
        for (int mt = 0; mt < 4; mt++) {
            float v0 = acc[mt][nt][0] + b0;
            float v1 = acc[mt][nt][1] + b1;
            float v2 = acc[mt][nt][2] + b0;
            float v3 = acc[mt][nt][3] + b1;
            unsigned long long c0 = ((unsigned long long)ordf(v0) << 32) | (uint32_t)(~colg);
            unsigned long long c1 = ((unsigned long long)ordf(v1) << 32) | (uint32_t)(~(colg + 1));
            unsigned long long c2 = ((unsigned long long)ordf(v2) << 32) | (uint32_t)(~colg);
            unsigned long long c3 = ((unsigned long long)ordf(v3) << 32) | (uint32_t)(~(colg + 1));
            if (c0 > best[mt * 2])     best[mt * 2]     = c0;
            if (c1 > best[mt * 2])     best[mt * 2]     = c1;
            if (c2 > best[mt * 2 + 1]) best[mt * 2 + 1] = c2;
            if (c3 > best[mt * 2 + 1]) best[mt * 2 + 1] = c3;
        }
    }
#pragma unroll
    for (int i = 0; i < 8; i++) {
        unsigned long long o1 = __shfl_xor_sync(0xffffffffu, best[i], 1);
        if (o1 > best[i]) best[i] = o1;
        unsigned long long o2 = __shfl_xor_sync(0xffffffffu, best[i], 2);
        if (o2 > best[i]) best[i] = o2;
    }
    if (t == 0) {
#pragma unroll
        for (int mt = 0; mt < 4; mt++)
#pragma unroll
            for (int half = 0; half < 2; half++) {
                int row = bm + wm + mt * 16 + g + half * 8;
                atomicMax(&g_best[row * G_NUM + gcol], best[mt * 2 + half]);
            }
    }
}

// ---------------------------------------------------------------------------
// Extract indices + histogram, gather, perplexity
// ---------------------------------------------------------------------------
__global__ void extract_kernel() {
    int i = blockIdx.x * blockDim.x + threadIdx.x;
    if (i >= M_TOTAL * G_NUM) return;
    unsigned long long b = g_best[i];
    int col = (int)(~(uint32_t)b);
    g_idx[i] = col;
    atomicAdd(&g_counts[(i & 1) * V_NUM + col], 1);
}

__global__ void gather_kernel(const float* __restrict__ cb,
                              float* __restrict__ out, int n4) {
    int e = blockIdx.x * blockDim.x + threadIdx.x;
    if (e >= n4) return;
    int m  = e >> 6;
    int c4 = e & 63;
    int g  = c4 >> 5;
    int d4 = c4 & 31;
    int id = g_idx[m * G_NUM + g];
    float4 v = *(const float4*)(cb + (size_t)(g * V_NUM + id) * DG + d4 * 4);
    *(float4*)(out + (size_t)e * 4) = v;
}

__global__ void perp_kernel(float* __restrict__ out_p) {
    __shared__ float partial[G_NUM * V_NUM];
    int t = threadIdx.x;
    if (t < G_NUM * V_NUM) {
        float m = (float)g_counts[t] * (1.0f / (float)M_TOTAL);
        partial[t] = m * logf(m + 1e-7f);
    }
    __syncthreads();
    if (t == 0) {
        float p = 0.0f;
        for (int g = 0; g < G_NUM; g++) {
            float s = 0.0f;
            for (int v = 0; v < V_NUM; v++) s += partial[g * V_NUM + v];
            p += expf(-s);
        }
        *out_p = p;
    }
}

// ---------------------------------------------------------------------------
// Launch
// ---------------------------------------------------------------------------
extern "C" void kernel_launch(void* const* d_in, const int* in_sizes, int n_in,
                              void* d_out, int out_size) {
    const float* hs = (const float*)d_in[0];   // (B,S,H)
    const float* W  = (const float*)d_in[1];   // (H, G*V)
    const float* b  = (const float*)d_in[2];   // (G*V,)
    const float* cb = (const float*)d_in[3];   // (1, G*V, Dg)
    float* out = (float*)d_out;

    cudaFuncSetAttribute(gemm_fp16_kernel,
                         cudaFuncAttributeMaxDynamicSharedMemorySize, SMEM_BYTES);

    init_kernel<<<(M_TOTAL * G_NUM + 255) / 256, 256>>>();
    splitA_kernel<<<(M_TOTAL * 32 + 255) / 256, 256>>>(hs);
    splitB_kernel<<<(80 * 32 * 32 + 255) / 256, 256>>>(W);

    dim3 grid(M_TOTAL / BM, N_DIM / BN);   // (256, 5)
    gemm_fp16_kernel<<<grid, 256, SMEM_BYTES>>>(b);

    extract_kernel<<<(M_TOTAL * G_NUM + 255) / 256, 256>>>();

    int n_out = M_TOTAL * G_NUM * DG;
    int n4 = n_out / 4;
    gather_kernel<<<(n4 + 255) / 256, 256>>>(cb, out, n4);

    if (out_size > n_out) {
        perp_kernel<<<1, G_NUM * V_NUM>>>(out + n_out);
    }
}

// round 7
// speedup vs baseline: 2.4390x; 1.1284x over previous
#include <cuda_runtime.h>
#include <cuda_fp16.h>
#include <math.h>
#include <stdint.h>

// ---------------------------------------------------------------------------
// Problem constants
// ---------------------------------------------------------------------------
#define M_TOTAL 32768      // B*S
#define K_DIM   512        // H
#define N_DIM   640        // G*V
#define G_NUM   2
#define V_NUM   320
#define DG      128
#define WSCALE  64.0f      // pre-scale on W and bias (argmax-invariant)

// GEMM tiling
#define BM 128
#define BN 128
#define BK 32
#define NKS (K_DIM / BK)        // 16 k-stages
#define A_ST 16384              // A stage bytes: 128 rows x 128B
#define B_ST 16384              // B stage bytes: 16 nt x 2 kb x 32 lanes x 16B
#define STAGE (A_ST + B_ST)     // 32768
#define NSTG 3
#define SMEM_BYTES (NSTG * STAGE)   // 98304

// ---------------------------------------------------------------------------
// Device-global scratch
// ---------------------------------------------------------------------------
__device__ uint4 g_asp[(size_t)M_TOTAL * 32 * 4];   // A split: per (m,kb16): h[16],m[16] = 64B
__device__ uint4 g_bsp[80 * 32 * 32];               // B split, frag-permuted: [nt][kb][lane]
__device__ unsigned long long g_best[M_TOTAL * G_NUM];
__device__ int g_idx[M_TOTAL * G_NUM];
__device__ int g_counts[G_NUM * V_NUM];

// ---------------------------------------------------------------------------
// Helpers
// ---------------------------------------------------------------------------
__device__ __forceinline__ uint32_t smem_u32(const void* p) {
    uint32_t a;
    asm("{ .reg .u64 t; cvta.to.shared.u64 t, %1; cvt.u32.u64 %0, t; }"
        : "=r"(a) : "l"(p));
    return a;
}

__device__ __forceinline__ void cp_async16(uint32_t dst, const void* src) {
    asm volatile("cp.async.cg.shared.global [%0], [%1], 16;"
                 :: "r"(dst), "l"(src) : "memory");
}

__device__ __forceinline__ void ldm_x4(uint32_t* r, uint32_t addr) {
    asm volatile("ldmatrix.sync.aligned.m8n8.x4.shared.b16 {%0,%1,%2,%3}, [%4];"
                 : "=r"(r[0]), "=r"(r[1]), "=r"(r[2]), "=r"(r[3]) : "r"(addr));
}

__device__ __forceinline__ void mma16(float* c, const uint32_t* a,
                                      uint32_t b0, uint32_t b1) {
    asm volatile(
        "mma.sync.aligned.m16n8k16.row.col.f32.f16.f16.f32 "
        "{%0,%1,%2,%3},{%4,%5,%6,%7},{%8,%9},{%0,%1,%2,%3};"
        : "+f"(c[0]), "+f"(c[1]), "+f"(c[2]), "+f"(c[3])
        : "r"(a[0]), "r"(a[1]), "r"(a[2]), "r"(a[3]), "r"(b0), "r"(b1));
}

__device__ __forceinline__ uint32_t packh2(__half a, __half b) {
    __half2 t = __halves2half2(a, b);
    return *reinterpret_cast<uint32_t*>(&t);
}

__device__ __forceinline__ uint32_t ordf(float v) {
    uint32_t u = __float_as_uint(v);
    return (u & 0x80000000u) ? ~u : (u | 0x80000000u);
}

// ---------------------------------------------------------------------------
// Init + pre-pass kernels
// ---------------------------------------------------------------------------
__global__ void init_kernel() {
    int i = blockIdx.x * blockDim.x + threadIdx.x;
    if (i < M_TOTAL * G_NUM) g_best[i] = 0ull;
    if (i < G_NUM * V_NUM) g_counts[i] = 0;
}

// A fp32 -> fp16 (h, m) per 16-k block: layout per (m, kb): [h 32B][m 32B]
__global__ void splitA_kernel(const float* __restrict__ A) {
    int id = blockIdx.x * blockDim.x + threadIdx.x;   // m*32 + kb
    if (id >= M_TOTAL * 32) return;
    const float* src = A + (size_t)id * 16;
    uint32_t hp[8], mp[8];
#pragma unroll
    for (int e = 0; e < 8; e++) {
        float x0 = src[2 * e], x1 = src[2 * e + 1];
        __half h0 = __float2half_rn(x0);
        __half h1 = __float2half_rn(x1);
        __half m0 = __float2half_rn(x0 - __half2float(h0));
        __half m1 = __float2half_rn(x1 - __half2float(h1));
        hp[e] = packh2(h0, h1);
        mp[e] = packh2(m0, m1);
    }
    uint4* dst = g_asp + (size_t)id * 4;
    dst[0] = make_uint4(hp[0], hp[1], hp[2], hp[3]);
    dst[1] = make_uint4(hp[4], hp[5], hp[6], hp[7]);
    dst[2] = make_uint4(mp[0], mp[1], mp[2], mp[3]);
    dst[3] = make_uint4(mp[4], mp[5], mp[6], mp[7]);
}

// W[k][n]*64 -> fp16 (h, m) b-fragments in exact per-lane mma order
__global__ void splitB_kernel(const float* __restrict__ W) {
    int id = blockIdx.x * blockDim.x + threadIdx.x;
    if (id >= 80 * 32 * 32) return;
    int l   = id & 31;
    int kb  = (id >> 5) & 31;
    int ntg = id >> 10;
    int k0  = kb * 16 + (l & 3) * 2;
    int n   = ntg * 8 + (l >> 2);

    float w0 = W[(size_t)(k0)     * N_DIM + n] * WSCALE;
    float w1 = W[(size_t)(k0 + 1) * N_DIM + n] * WSCALE;
    float w8 = W[(size_t)(k0 + 8) * N_DIM + n] * WSCALE;
    float w9 = W[(size_t)(k0 + 9) * N_DIM + n] * WSCALE;

    __half h0 = __float2half_rn(w0), h1 = __float2half_rn(w1);
    __half h8 = __float2half_rn(w8), h9 = __float2half_rn(w9);
    __half m0 = __float2half_rn(w0 - __half2float(h0));
    __half m1 = __float2half_rn(w1 - __half2float(h1));
    __half m8 = __float2half_rn(w8 - __half2float(h8));
    __half m9 = __float2half_rn(w9 - __half2float(h9));

    g_bsp[id] = make_uint4(packh2(h0, h1), packh2(h8, h9),
                           packh2(m0, m1), packh2(m8, m9));
}

// ---------------------------------------------------------------------------
// fp16 2-way split, 3-term (hh + hm + mh) GEMM with fused bias + argmax
// grid (256, 5), 256 threads, 8 warps 2(m) x 4(n), warp tile 64x32
// ---------------------------------------------------------------------------
__global__ __launch_bounds__(256, 2)
void gemm_fp16_kernel(const float* __restrict__ bias) {
    extern __shared__ char smem[];
    const uint32_t sb = smem_u32(smem);
    const int tid  = threadIdx.x;
    const int wid  = tid >> 5;
    const int lane = tid & 31;
    const int g    = lane >> 2;       // C row within 8
    const int t    = lane & 3;        // C col pair
    const int wm   = (wid & 1) * 64;
    const int wn   = (wid >> 1) * 32;
    const int bm   = blockIdx.x * BM;
    const int by   = blockIdx.y;
    const int bn   = by * BN;

    // ldmatrix row/chunk assignment for this lane
    const int lrow_off = ((lane >> 3) & 1) * 8 + (lane & 7);
    const int lkh      = lane >> 4;   // 0..1 : which 16B chunk of the k16

    float acc[4][4][4];
#pragma unroll
    for (int a = 0; a < 4; a++)
#pragma unroll
        for (int b = 0; b < 4; b++)
#pragma unroll
            for (int c = 0; c < 4; c++) acc[a][b][c] = 0.0f;

    auto load_stage = [&](int s) {
        int buf = s % NSTG;
        uint32_t Asm = sb + buf * STAGE;
        uint32_t Bsm = Asm + A_ST;
        // A: 1024 x 16B, SW128 XOR swizzle
#pragma unroll
        for (int i = 0; i < 4; i++) {
            int c   = tid + i * 256;
            int row = c >> 3;
            int q   = c & 7;
            const char* src = (const char*)g_asp + (size_t)(bm + row) * 2048
                            + s * 128 + q * 16;
            cp_async16(Asm + row * 128 + ((q ^ (row & 7)) * 16), src);
        }
        // B: 1024 x 16B, already fragment-ordered
#pragma unroll
        for (int i = 0; i < 4; i++) {
            int c  = tid + i * 256;
            int nt = c >> 6;
            int j  = (c >> 5) & 1;
            int ln = c & 31;
            const char* src = (const char*)g_bsp +
                ((size_t)((by * 16 + nt) * 32 + s * 2 + j) * 32 + ln) * 16;
            cp_async16(Bsm + c * 16, src);
        }
        asm volatile("cp.async.commit_group;" ::: "memory");
    };

    auto compute = [&](int buf) {
        uint32_t Asm = sb + buf * STAGE;
        const uint4* Bp = (const uint4*)(smem + buf * STAGE + A_ST);
#pragma unroll
        for (int j = 0; j < 2; j++) {
            uint32_t ah[4][4], am[4][4];
#pragma unroll
            for (int mt = 0; mt < 4; mt++) {
                int row = wm + mt * 16 + lrow_off;
                uint32_t base = Asm + row * 128;
                uint32_t ch = ((j << 2) + lkh)     ^ (row & 7);
                uint32_t cm = ((j << 2) + 2 + lkh) ^ (row & 7);
                ldm_x4(ah[mt], base + ch * 16);
                ldm_x4(am[mt], base + cm * 16);
            }
            uint4 bv[4];
#pragma unroll
            for (int nt = 0; nt < 4; nt++)
                bv[nt] = Bp[(((wn >> 3) + nt) * 2 + j) * 32 + lane];
#pragma unroll
            for (int mt = 0; mt < 4; mt++)
#pragma unroll
                for (int nt = 0; nt < 4; nt++) {
                    mma16(acc[mt][nt], ah[mt], bv[nt].x, bv[nt].y);  // hh
                    mma16(acc[mt][nt], ah[mt], bv[nt].z, bv[nt].w);  // hm
                    mma16(acc[mt][nt], am[mt], bv[nt].x, bv[nt].y);  // mh
                    // mm term dropped: contributes ~2^-22 relative, ~0.05
                    // expected argmax flips over the whole problem.
                }
        }
    };

    load_stage(0);
    load_stage(1);
    for (int s = 0; s < NKS; s++) {
        if (s < NKS - 2)
            asm volatile("cp.async.wait_group 1;" ::: "memory");
        else
            asm volatile("cp.async.wait_group 0;" ::: "memory");
        __syncthreads();
        if (s + 2 < NKS) load_stage(s + 2);
        compute(s % NSTG);
    }

    // ---- fused epilogue: scaled bias + packed argmax + atomicMax ----
    const int gcol    = ((bn + wn) >= V_NUM) ? 1 : 0;
    const int colbase = bn + wn - gcol * V_NUM;

    unsigned long long best[8];
#pragma unroll
    for (int i = 0; i < 8; i++) best[i] = 0ull;

#pragma unroll
    for (int nt = 0; nt < 4; nt++) {
        int colg = colbase + nt * 8 + 2 * t;
        float b0 = bias[bn + wn + nt * 8 + 2 * t]     * WSCALE;
        float b1 = bias[bn + wn + nt * 8 + 2 * t + 1] * WSCALE;
#pragma unroll
        for (int mt = 0; mt < 4; mt++) {
            float v0 = acc[mt][nt][0] + b0;
            float v1 = acc[mt][nt][1] + b1;
            float v2 = acc[mt][nt][2] + b0;
            float v3 = acc[mt][nt][3] + b1;
            unsigned long long c0 = ((unsigned long long)ordf(v0) << 32) | (uint32_t)(~colg);
            unsigned long long c1 = ((unsigned long long)ordf(v1) << 32) | (uint32_t)(~(colg + 1));
            unsigned long long c2 = ((unsigned long long)ordf(v2) << 32) | (uint32_t)(~colg);
            unsigned long long c3 = ((unsigned long long)ordf(v3) << 32) | (uint32_t)(~(colg + 1));
            if (c0 > best[mt * 2])     best[mt * 2]     = c0;
            if (c1 > best[mt * 2])     best[mt * 2]     = c1;
            if (c2 > best[mt * 2 + 1]) best[mt * 2 + 1] = c2;
            if (c3 > best[mt * 2 + 1]) best[mt * 2 + 1] = c3;
        }
    }
#pragma unroll
    for (int i = 0; i < 8; i++) {
        unsigned long long o1 = __shfl_xor_sync(0xffffffffu, best[i], 1);
        if (o1 > best[i]) best[i] = o1;
        unsigned long long o2 = __shfl_xor_sync(0xffffffffu, best[i], 2);
        if (o2 > best[i]) best[i] = o2;
    }
    if (t == 0) {
#pragma unroll
        for (int mt = 0; mt < 4; mt++)
#pragma unroll
            for (int half = 0; half < 2; half++) {
                int row = bm + wm + mt * 16 + g + half * 8;
                atomicMax(&g_best[row * G_NUM + gcol], best[mt * 2 + half]);
            }
    }
}

// ---------------------------------------------------------------------------
// Extract indices + histogram, gather, perplexity
// ---------------------------------------------------------------------------
__global__ void extract_kernel() {
    int i = blockIdx.x * blockDim.x + threadIdx.x;
    if (i >= M_TOTAL * G_NUM) return;
    unsigned long long b = g_best[i];
    int col = (int)(~(uint32_t)b);
    g_idx[i] = col;
    atomicAdd(&g_counts[(i & 1) * V_NUM + col], 1);
}

__global__ void gather_kernel(const float* __restrict__ cb,
                              float* __restrict__ out, int n4) {
    int e = blockIdx.x * blockDim.x + threadIdx.x;
    if (e >= n4) return;
    int m  = e >> 6;
    int c4 = e & 63;
    int g  = c4 >> 5;
    int d4 = c4 & 31;
    int id = g_idx[m * G_NUM + g];
    float4 v = *(const float4*)(cb + (size_t)(g * V_NUM + id) * DG + d4 * 4);
    *(float4*)(out + (size_t)e * 4) = v;
}

__global__ void perp_kernel(float* __restrict__ out_p) {
    __shared__ float partial[G_NUM * V_NUM];
    int t = threadIdx.x;
    if (t < G_NUM * V_NUM) {
        float m = (float)g_counts[t] * (1.0f / (float)M_TOTAL);
        partial[t] = m * logf(m + 1e-7f);
    }
    __syncthreads();
    if (t == 0) {
        float p = 0.0f;
        for (int g = 0; g < G_NUM; g++) {
            float s = 0.0f;
            for (int v = 0; v < V_NUM; v++) s += partial[g * V_NUM + v];
            p += expf(-s);
        }
        *out_p = p;
    }
}

// ---------------------------------------------------------------------------
// Launch
// ---------------------------------------------------------------------------
extern "C" void kernel_launch(void* const* d_in, const int* in_sizes, int n_in,
                              void* d_out, int out_size) {
    const float* hs = (const float*)d_in[0];   // (B,S,H)
    const float* W  = (const float*)d_in[1];   // (H, G*V)
    const float* b  = (const float*)d_in[2];   // (G*V,)
    const float* cb = (const float*)d_in[3];   // (1, G*V, Dg)
    float* out = (float*)d_out;

    cudaFuncSetAttribute(gemm_fp16_kernel,
                         cudaFuncAttributeMaxDynamicSharedMemorySize, SMEM_BYTES);

    init_kernel<<<(M_TOTAL * G_NUM + 255) / 256, 256>>>();
    splitA_kernel<<<(M_TOTAL * 32 + 255) / 256, 256>>>(hs);
    splitB_kernel<<<(80 * 32 * 32 + 255) / 256, 256>>>(W);

    dim3 grid(M_TOTAL / BM, N_DIM / BN);   // (256, 5)
    gemm_fp16_kernel<<<grid, 256, SMEM_BYTES>>>(b);

    extract_kernel<<<(M_TOTAL * G_NUM + 255) / 256, 256>>>();

    int n_out = M_TOTAL * G_NUM * DG;
    int n4 = n_out / 4;
    gather_kernel<<<(n4 + 255) / 256, 256>>>(cb, out, n4);

    if (out_size > n_out) {
        perp_kernel<<<1, G_NUM * V_NUM>>>(out + n_out);
    }
}